// round 2
// baseline (speedup 1.0000x reference)
#include <cuda_runtime.h>

#define NN 50000
#define DD 128
#define NE 800000

// Scratch: device globals (no allocation allowed in kernel_launch).
__device__ float g_acc[NN * DD];
__device__ float g_hA[NN * DD];
__device__ float g_hB[NN * DD];
__device__ int   g_src[NE];
__device__ int   g_dst[NE];

// ---------------------------------------------------------------------------
// Convert edge_index to canonical int32, auto-detecting int32 vs int64 layout.
// If int64 (little-endian), odd 32-bit words are high words of values in
// [0, 50000) and are all zero; if int32 they are random node ids.
// ---------------------------------------------------------------------------
__global__ void convert_idx_k(const unsigned int* __restrict__ w,
                              int* __restrict__ src, int* __restrict__ dst) {
    bool is64 = true;
#pragma unroll
    for (int j = 1; j < 64; j += 2)
        if (w[j] != 0u) { is64 = false; break; }
    int i = blockIdx.x * blockDim.x + threadIdx.x;
    if (i >= 2 * NE) return;
    int v = is64 ? (int)w[2 * (long long)i] : (int)w[i];
    if (i < NE) src[i] = v;
    else        dst[i - NE] = v;
}

// ---------------------------------------------------------------------------
// acc = src  (vectorized copy; initializes accumulator to h so the scatter
// produces h + neigh directly)
// ---------------------------------------------------------------------------
__global__ void copy_k(float4* __restrict__ d, const float4* __restrict__ s, int n) {
    int i = blockIdx.x * blockDim.x + threadIdx.x;
    if (i < n) d[i] = s[i];
}

// ---------------------------------------------------------------------------
// scatter: acc[dst[e]] += h[src[e]]  — one thread per (edge, 16B chunk),
// warp = one edge so the 512B row gather and reduction are fully coalesced.
// red.global.add.v4.f32: vector reduction, no return trip.
// ---------------------------------------------------------------------------
__global__ void scatter_k(const float* __restrict__ h,
                          const int* __restrict__ srcv,
                          const int* __restrict__ dstv,
                          float* __restrict__ acc) {
    long long i = (long long)blockIdx.x * blockDim.x + threadIdx.x;
    if (i >= (long long)NE * 32) return;
    int e = (int)(i >> 5);
    int c = (int)(i & 31);
    int s = srcv[e];
    int d = dstv[e];
    float4 v = ((const float4*)(h + (size_t)s * DD))[c];
    float* p = acc + (size_t)d * DD + c * 4;
    asm volatile("red.global.add.v4.f32 [%0], {%1,%2,%3,%4};"
                 :: "l"(p), "f"(v.x), "f"(v.y), "f"(v.z), "f"(v.w)
                 : "memory");
}

// ---------------------------------------------------------------------------
// Fused MLP: Y = relu(X @ W1 + b1) @ W2 + b2 (+ RES)
// 512 threads = 16 warps; each warp owns 4 rows; each lane owns 4 columns
// (cols 4*lane..4*lane+3). Both weights resident in shared. Intermediate t
// lives in registers, re-staged through the same smem row buffer.
// ---------------------------------------------------------------------------
#define FMA4(W, xs, A)                                                        \
    do { (A).x += (xs) * (W).x; (A).y += (xs) * (W).y;                        \
         (A).z += (xs) * (W).z; (A).w += (xs) * (W).w; } while (0)

__device__ __forceinline__ void gemm_rows4(const float4* __restrict__ swv,
                                           const float4* __restrict__ myt,
                                           int lane,
                                           float4& a0, float4& a1,
                                           float4& a2, float4& a3) {
#pragma unroll 4
    for (int k = 0; k < DD; k += 4) {
        int k4 = k >> 2;
        float4 x0 = myt[0 * 32 + k4];
        float4 x1 = myt[1 * 32 + k4];
        float4 x2 = myt[2 * 32 + k4];
        float4 x3 = myt[3 * 32 + k4];
        float4 w;
        w = swv[(k + 0) * 32 + lane];
        FMA4(w, x0.x, a0); FMA4(w, x1.x, a1); FMA4(w, x2.x, a2); FMA4(w, x3.x, a3);
        w = swv[(k + 1) * 32 + lane];
        FMA4(w, x0.y, a0); FMA4(w, x1.y, a1); FMA4(w, x2.y, a2); FMA4(w, x3.y, a3);
        w = swv[(k + 2) * 32 + lane];
        FMA4(w, x0.z, a0); FMA4(w, x1.z, a1); FMA4(w, x2.z, a2); FMA4(w, x3.z, a3);
        w = swv[(k + 3) * 32 + lane];
        FMA4(w, x0.w, a0); FMA4(w, x1.w, a1); FMA4(w, x2.w, a2); FMA4(w, x3.w, a3);
    }
}

__device__ __forceinline__ void relu4(float4& a) {
    a.x = fmaxf(a.x, 0.f); a.y = fmaxf(a.y, 0.f);
    a.z = fmaxf(a.z, 0.f); a.w = fmaxf(a.w, 0.f);
}

// dynamic smem: sw1[16384] sw2[16384] sb1[128] sb2[128] st[16*4*128=8192]
#define MLP_SMEM_FLOATS (16384 + 16384 + 128 + 128 + 8192)
#define MLP_SMEM_BYTES  (MLP_SMEM_FLOATS * 4)

__global__ __launch_bounds__(512, 1) void mlp_k(
    const float* __restrict__ X,
    const float* __restrict__ W1, const float* __restrict__ B1,
    const float* __restrict__ W2, const float* __restrict__ B2,
    const float* __restrict__ RES, float* __restrict__ Y) {
    extern __shared__ float sm[];
    float* sw1 = sm;
    float* sw2 = sm + 16384;
    float* sb1 = sm + 32768;
    float* sb2 = sm + 32896;
    float* st  = sm + 33024;

    int tid = threadIdx.x;
#pragma unroll 4
    for (int i = tid; i < DD * DD; i += 512) { sw1[i] = W1[i]; sw2[i] = W2[i]; }
    if (tid < DD) sb1[tid] = B1[tid];
    else if (tid < 2 * DD) sb2[tid - DD] = B2[tid - DD];
    __syncthreads();

    int warp = tid >> 5, lane = tid & 31;
    int r0 = (blockIdx.x * 16 + warp) * 4;
    float4* myt = (float4*)(st + warp * 4 * DD);  // [4 rows][32 float4]

    // stage X rows
#pragma unroll
    for (int r = 0; r < 4; r++) {
        int row = r0 + r;
        float4 v = make_float4(0.f, 0.f, 0.f, 0.f);
        if (row < NN) v = ((const float4*)(X + (size_t)row * DD))[lane];
        myt[r * 32 + lane] = v;
    }
    __syncwarp();

    float4 a0, a1, a2, a3;
    { float4 b = ((const float4*)sb1)[lane]; a0 = b; a1 = b; a2 = b; a3 = b; }
    gemm_rows4((const float4*)sw1, myt, lane, a0, a1, a2, a3);
    relu4(a0); relu4(a1); relu4(a2); relu4(a3);

    __syncwarp();
    myt[0 * 32 + lane] = a0;
    myt[1 * 32 + lane] = a1;
    myt[2 * 32 + lane] = a2;
    myt[3 * 32 + lane] = a3;
    __syncwarp();

    { float4 b = ((const float4*)sb2)[lane]; a0 = b; a1 = b; a2 = b; a3 = b; }
    gemm_rows4((const float4*)sw2, myt, lane, a0, a1, a2, a3);

#pragma unroll
    for (int r = 0; r < 4; r++) {
        int row = r0 + r;
        if (row >= NN) continue;
        float4 o = (r == 0) ? a0 : (r == 1) ? a1 : (r == 2) ? a2 : a3;
        if (RES) {
            float4 rv = ((const float4*)(RES + (size_t)row * DD))[lane];
            o.x += rv.x; o.y += rv.y; o.z += rv.z; o.w += rv.w;
        }
        ((float4*)(Y + (size_t)row * DD))[lane] = o;
    }
}

// ---------------------------------------------------------------------------
// Head: OUT = X @ WH + bh   (single GEMM, same blocking)
// ---------------------------------------------------------------------------
#define HEAD_SMEM_FLOATS (16384 + 128 + 8192)
#define HEAD_SMEM_BYTES  (HEAD_SMEM_FLOATS * 4)

__global__ __launch_bounds__(512, 1) void head_k(
    const float* __restrict__ X,
    const float* __restrict__ WH, const float* __restrict__ BH,
    float* __restrict__ Y) {
    extern __shared__ float sm[];
    float* sw = sm;
    float* sb = sm + 16384;
    float* st = sm + 16512;

    int tid = threadIdx.x;
#pragma unroll 4
    for (int i = tid; i < DD * DD; i += 512) sw[i] = WH[i];
    if (tid < DD) sb[tid] = BH[tid];
    __syncthreads();

    int warp = tid >> 5, lane = tid & 31;
    int r0 = (blockIdx.x * 16 + warp) * 4;
    float4* myt = (float4*)(st + warp * 4 * DD);

#pragma unroll
    for (int r = 0; r < 4; r++) {
        int row = r0 + r;
        float4 v = make_float4(0.f, 0.f, 0.f, 0.f);
        if (row < NN) v = ((const float4*)(X + (size_t)row * DD))[lane];
        myt[r * 32 + lane] = v;
    }
    __syncwarp();

    float4 a0, a1, a2, a3;
    { float4 b = ((const float4*)sb)[lane]; a0 = b; a1 = b; a2 = b; a3 = b; }
    gemm_rows4((const float4*)sw, myt, lane, a0, a1, a2, a3);

#pragma unroll
    for (int r = 0; r < 4; r++) {
        int row = r0 + r;
        if (row >= NN) continue;
        float4 o = (r == 0) ? a0 : (r == 1) ? a1 : (r == 2) ? a2 : a3;
        ((float4*)(Y + (size_t)row * DD))[lane] = o;
    }
}

// ---------------------------------------------------------------------------
// Launch
// ---------------------------------------------------------------------------
extern "C" void kernel_launch(void* const* d_in, const int* in_sizes, int n_in,
                              void* d_out, int out_size) {
    const float* x      = (const float*)d_in[0];
    const unsigned int* ei = (const unsigned int*)d_in[1];
    const float* w1_0 = (const float*)d_in[2];
    const float* b1_0 = (const float*)d_in[3];
    const float* w2_0 = (const float*)d_in[4];
    const float* b2_0 = (const float*)d_in[5];
    const float* w1_1 = (const float*)d_in[6];
    const float* b1_1 = (const float*)d_in[7];
    const float* w2_1 = (const float*)d_in[8];
    const float* b2_1 = (const float*)d_in[9];
    const float* w1_2 = (const float*)d_in[10];
    const float* b1_2 = (const float*)d_in[11];
    const float* w2_2 = (const float*)d_in[12];
    const float* b2_2 = (const float*)d_in[13];
    const float* wh   = (const float*)d_in[14];
    const float* bh   = (const float*)d_in[15];
    float* out = (float*)d_out;

    float *acc, *hA, *hB;
    int *src, *dst;
    cudaGetSymbolAddress((void**)&acc, g_acc);
    cudaGetSymbolAddress((void**)&hA, g_hA);
    cudaGetSymbolAddress((void**)&hB, g_hB);
    cudaGetSymbolAddress((void**)&src, g_src);
    cudaGetSymbolAddress((void**)&dst, g_dst);

    cudaFuncSetAttribute(mlp_k, cudaFuncAttributeMaxDynamicSharedMemorySize,
                         MLP_SMEM_BYTES);
    cudaFuncSetAttribute(head_k, cudaFuncAttributeMaxDynamicSharedMemorySize,
                         HEAD_SMEM_BYTES);

    const int n4  = NN * DD / 4;
    const int cpB = (n4 + 255) / 256;
    const long long sct = (long long)NE * 32;
    const int scB = (int)((sct + 255) / 256);
    const int mlB = (NN + 63) / 64;
    const int cvB = (2 * NE + 255) / 256;

    // Canonicalize edge indices (handles int32 or int64 input layout).
    convert_idx_k<<<cvB, 256>>>(ei, src, dst);

    // Layer 0 (residual = x)
    copy_k<<<cpB, 256>>>((float4*)acc, (const float4*)x, n4);
    scatter_k<<<scB, 256>>>(x, src, dst, acc);
    mlp_k<<<mlB, 512, MLP_SMEM_BYTES>>>(acc, w1_0, b1_0, w2_0, b2_0, x, hA);

    // Layer 1 (residual = hA)
    copy_k<<<cpB, 256>>>((float4*)acc, (const float4*)hA, n4);
    scatter_k<<<scB, 256>>>(hA, src, dst, acc);
    mlp_k<<<mlB, 512, MLP_SMEM_BYTES>>>(acc, w1_1, b1_1, w2_1, b2_1, hA, hB);

    // Layer 2 (no residual)
    copy_k<<<cpB, 256>>>((float4*)acc, (const float4*)hB, n4);
    scatter_k<<<scB, 256>>>(hB, src, dst, acc);
    mlp_k<<<mlB, 512, MLP_SMEM_BYTES>>>(acc, w1_2, b1_2, w2_2, b2_2, nullptr, hA);

    // Head
    head_k<<<mlB, 512, HEAD_SMEM_BYTES>>>(hA, wh, bh, out);
}

// round 3
// speedup vs baseline: 1.3618x; 1.3618x over previous
#include <cuda_runtime.h>

#define NN 50000
#define DD 128
#define NE 800000

// Scratch: device globals (no allocation allowed in kernel_launch).
__device__ float g_acc[NN * DD];
__device__ float g_hA[NN * DD];
__device__ float g_hB[NN * DD];
__device__ int   g_src[NE];
__device__ int   g_dst[NE];
__device__ int   g_cnt[NN + 1];   // degree histogram -> row_start after scan
__device__ int   g_cur[NN];       // running fill cursor per node
__device__ int   g_csr[NE];       // src ids grouped by dst

// ---------------------------------------------------------------------------
// Convert edge_index to canonical int32, auto-detecting int32 vs int64 layout.
// If int64 (LE), odd 32-bit words are high words of values in [0,50000): all 0.
// ---------------------------------------------------------------------------
__global__ void convert_idx_k(const unsigned int* __restrict__ w,
                              int* __restrict__ src, int* __restrict__ dst) {
    bool is64 = true;
#pragma unroll
    for (int j = 1; j < 64; j += 2)
        if (w[j] != 0u) { is64 = false; break; }
    int i = blockIdx.x * blockDim.x + threadIdx.x;
    if (i >= 2 * NE) return;
    int v = is64 ? (int)w[2 * (long long)i] : (int)w[i];
    if (i < NE) src[i] = v;
    else        dst[i - NE] = v;
}

// ---------------------------------------------------------------------------
// CSR build: histogram of in-degrees (offset by +1 for scan convenience)
// ---------------------------------------------------------------------------
__global__ void hist_k(const int* __restrict__ dst, int* __restrict__ cnt) {
    int e = blockIdx.x * blockDim.x + threadIdx.x;
    if (e < NE) atomicAdd(&cnt[dst[e] + 1], 1);
}

// Single-block inclusive scan over cnt[0..NN]; writes row_start in place and
// initializes cur[] = row_start.
__global__ void scan_k(int* __restrict__ cnt, int* __restrict__ cur) {
    __shared__ int part[1024];
    const int TOT = NN + 1;
    const int CH = (TOT + 1023) / 1024;
    int t = threadIdx.x;
    int beg = t * CH;
    int end = beg + CH; if (end > TOT) end = TOT;
    int sum = 0;
    for (int i = beg; i < end; i++) sum += cnt[i];
    part[t] = sum;
    __syncthreads();
    for (int off = 1; off < 1024; off <<= 1) {
        int add = (t >= off) ? part[t - off] : 0;
        __syncthreads();
        part[t] += add;
        __syncthreads();
    }
    int run = (t == 0) ? 0 : part[t - 1];
    for (int i = beg; i < end; i++) {
        run += cnt[i];
        cnt[i] = run;
        if (i < NN) cur[i] = run;
    }
}

__global__ void fill_k(const int* __restrict__ src, const int* __restrict__ dst,
                       int* __restrict__ cur, int* __restrict__ csr) {
    int e = blockIdx.x * blockDim.x + threadIdx.x;
    if (e >= NE) return;
    int p = atomicAdd(&cur[dst[e]], 1);
    csr[p] = src[e];
}

// ---------------------------------------------------------------------------
// Aggregation: acc[node] = h[node] + sum_{src in in(node)} h[src]
// One warp per node; lane owns one float4 (16B) of the 512B row.
// No atomics: pure coalesced gather + single write.
// ---------------------------------------------------------------------------
__global__ __launch_bounds__(256) void agg_k(const float* __restrict__ h,
                                             const int* __restrict__ rs,
                                             const int* __restrict__ csr,
                                             float* __restrict__ acc) {
    int warp = threadIdx.x >> 5, lane = threadIdx.x & 31;
    int node = blockIdx.x * 8 + warp;
    if (node >= NN) return;
    float4 a = ((const float4*)(h + (size_t)node * DD))[lane];
    int beg = rs[node], end = rs[node + 1];
#pragma unroll 4
    for (int j = beg; j < end; j++) {
        int s = csr[j];
        float4 v = ((const float4*)(h + (size_t)s * DD))[lane];
        a.x += v.x; a.y += v.y; a.z += v.z; a.w += v.w;
    }
    ((float4*)(acc + (size_t)node * DD))[lane] = a;
}

// ---------------------------------------------------------------------------
// Fused MLP: Y = relu(X @ W1 + b1) @ W2 + b2 (+ RES) [@ WH + bh]
// 512 threads = 16 warps; each warp owns 8 rows; lane owns 4 cols.
// Both weights in smem; per-warp row tiles in smem; accumulators in regs.
// Optional 3rd GEMM (head) reloads WH into the sw1 region.
// ---------------------------------------------------------------------------
#define FMA4(W, xs, A)                                                        \
    do { (A).x += (xs) * (W).x; (A).y += (xs) * (W).y;                        \
         (A).z += (xs) * (W).z; (A).w += (xs) * (W).w; } while (0)

__device__ __forceinline__ void gemm_rows8(const float4* __restrict__ swv,
                                           const float4* __restrict__ myt,
                                           int lane, float4* __restrict__ a) {
#pragma unroll 2
    for (int k4 = 0; k4 < 32; k4++) {
        float4 xv[8];
#pragma unroll
        for (int r = 0; r < 8; r++) xv[r] = myt[r * 32 + k4];
#pragma unroll
        for (int kk = 0; kk < 4; kk++) {
            float4 w = swv[(k4 * 4 + kk) * 32 + lane];
#pragma unroll
            for (int r = 0; r < 8; r++) {
                float xs = (kk == 0) ? xv[r].x : (kk == 1) ? xv[r].y
                         : (kk == 2) ? xv[r].z : xv[r].w;
                FMA4(w, xs, a[r]);
            }
        }
    }
}

__device__ __forceinline__ void relu4(float4& a) {
    a.x = fmaxf(a.x, 0.f); a.y = fmaxf(a.y, 0.f);
    a.z = fmaxf(a.z, 0.f); a.w = fmaxf(a.w, 0.f);
}

// dyn smem: sw1[16384] sw2[16384] sb1[128] sb2[128] st[16*8*128=16384] floats
#define MLP_SMEM_FLOATS (16384 + 16384 + 128 + 128 + 16384)
#define MLP_SMEM_BYTES  (MLP_SMEM_FLOATS * 4)

__global__ __launch_bounds__(512, 1) void mlp_k(
    const float* __restrict__ X,
    const float* __restrict__ W1, const float* __restrict__ B1,
    const float* __restrict__ W2, const float* __restrict__ B2,
    const float* __restrict__ RES,
    const float* __restrict__ WH, const float* __restrict__ BH,
    float* __restrict__ Y) {
    extern __shared__ float sm[];
    float* sw1 = sm;
    float* sw2 = sm + 16384;
    float* sb1 = sm + 32768;
    float* sb2 = sm + 32896;
    float* st  = sm + 33024;

    int tid = threadIdx.x;
    {   // vectorized weight staging
        float4* dw1 = (float4*)sw1; const float4* s1 = (const float4*)W1;
        float4* dw2 = (float4*)sw2; const float4* s2 = (const float4*)W2;
#pragma unroll 8
        for (int i = tid; i < DD * DD / 4; i += 512) { dw1[i] = s1[i]; dw2[i] = s2[i]; }
        if (tid < DD) sb1[tid] = B1[tid];
        else if (tid < 2 * DD) sb2[tid - DD] = B2[tid - DD];
    }
    __syncthreads();

    int warp = tid >> 5, lane = tid & 31;
    int r0 = (blockIdx.x * 16 + warp) * 8;
    float4* myt = (float4*)(st + warp * 8 * DD);  // [8 rows][32 float4]

    // stage X rows
#pragma unroll
    for (int r = 0; r < 8; r++) {
        int row = r0 + r;
        float4 v = make_float4(0.f, 0.f, 0.f, 0.f);
        if (row < NN) v = ((const float4*)(X + (size_t)row * DD))[lane];
        myt[r * 32 + lane] = v;
    }
    __syncwarp();

    float4 a[8];
    {   float4 b = ((const float4*)sb1)[lane];
#pragma unroll
        for (int r = 0; r < 8; r++) a[r] = b; }
    gemm_rows8((const float4*)sw1, myt, lane, a);
#pragma unroll
    for (int r = 0; r < 8; r++) relu4(a[r]);

    __syncwarp();
#pragma unroll
    for (int r = 0; r < 8; r++) myt[r * 32 + lane] = a[r];
    __syncwarp();

    {   float4 b = ((const float4*)sb2)[lane];
#pragma unroll
        for (int r = 0; r < 8; r++) a[r] = b; }
    gemm_rows8((const float4*)sw2, myt, lane, a);

    if (RES) {
#pragma unroll
        for (int r = 0; r < 8; r++) {
            int row = r0 + r;
            if (row < NN) {
                float4 rv = ((const float4*)(RES + (size_t)row * DD))[lane];
                a[r].x += rv.x; a[r].y += rv.y; a[r].z += rv.z; a[r].w += rv.w;
            }
        }
    }

    if (WH) {
        // Fused head GEMM: reload WH into sw1 region, BH into sb1.
        __syncthreads();
        {   float4* dw = (float4*)sw1; const float4* s = (const float4*)WH;
#pragma unroll 8
            for (int i = tid; i < DD * DD / 4; i += 512) dw[i] = s[i];
            if (tid < DD) sb1[tid] = BH[tid];
        }
        __syncthreads();
#pragma unroll
        for (int r = 0; r < 8; r++) myt[r * 32 + lane] = a[r];
        __syncwarp();
        {   float4 b = ((const float4*)sb1)[lane];
#pragma unroll
            for (int r = 0; r < 8; r++) a[r] = b; }
        gemm_rows8((const float4*)sw1, myt, lane, a);
    }

#pragma unroll
    for (int r = 0; r < 8; r++) {
        int row = r0 + r;
        if (row < NN)
            ((float4*)(Y + (size_t)row * DD))[lane] = a[r];
    }
}

// ---------------------------------------------------------------------------
// Launch
// ---------------------------------------------------------------------------
extern "C" void kernel_launch(void* const* d_in, const int* in_sizes, int n_in,
                              void* d_out, int out_size) {
    const float* x      = (const float*)d_in[0];
    const unsigned int* ei = (const unsigned int*)d_in[1];
    const float* w1_0 = (const float*)d_in[2];
    const float* b1_0 = (const float*)d_in[3];
    const float* w2_0 = (const float*)d_in[4];
    const float* b2_0 = (const float*)d_in[5];
    const float* w1_1 = (const float*)d_in[6];
    const float* b1_1 = (const float*)d_in[7];
    const float* w2_1 = (const float*)d_in[8];
    const float* b2_1 = (const float*)d_in[9];
    const float* w1_2 = (const float*)d_in[10];
    const float* b1_2 = (const float*)d_in[11];
    const float* w2_2 = (const float*)d_in[12];
    const float* b2_2 = (const float*)d_in[13];
    const float* wh   = (const float*)d_in[14];
    const float* bh   = (const float*)d_in[15];
    float* out = (float*)d_out;

    float *acc, *hA, *hB;
    int *src, *dst, *cnt, *cur, *csr;
    cudaGetSymbolAddress((void**)&acc, g_acc);
    cudaGetSymbolAddress((void**)&hA, g_hA);
    cudaGetSymbolAddress((void**)&hB, g_hB);
    cudaGetSymbolAddress((void**)&src, g_src);
    cudaGetSymbolAddress((void**)&dst, g_dst);
    cudaGetSymbolAddress((void**)&cnt, g_cnt);
    cudaGetSymbolAddress((void**)&cur, g_cur);
    cudaGetSymbolAddress((void**)&csr, g_csr);

    cudaFuncSetAttribute(mlp_k, cudaFuncAttributeMaxDynamicSharedMemorySize,
                         MLP_SMEM_BYTES);

    const int cvB = (2 * NE + 255) / 256;
    const int heB = (NE + 255) / 256;
    const int agB = (NN + 7) / 8;
    const int mlB = (NN + 127) / 128;

    // --- Preprocessing: canonical indices + CSR (grouped by dst) ---
    convert_idx_k<<<cvB, 256>>>(ei, src, dst);
    cudaMemsetAsync(cnt, 0, (NN + 1) * sizeof(int));
    hist_k<<<heB, 256>>>(dst, cnt);
    scan_k<<<1, 1024>>>(cnt, cur);
    fill_k<<<heB, 256>>>(src, dst, cur, csr);

    // --- Layer 0 (residual = x) ---
    agg_k<<<agB, 256>>>(x, cnt, csr, acc);
    mlp_k<<<mlB, 512, MLP_SMEM_BYTES>>>(acc, w1_0, b1_0, w2_0, b2_0, x,
                                        nullptr, nullptr, hA);
    // --- Layer 1 (residual = hA) ---
    agg_k<<<agB, 256>>>(hA, cnt, csr, acc);
    mlp_k<<<mlB, 512, MLP_SMEM_BYTES>>>(acc, w1_1, b1_1, w2_1, b2_1, hA,
                                        nullptr, nullptr, hB);
    // --- Layer 2 (no residual) + fused head ---
    agg_k<<<agB, 256>>>(hB, cnt, csr, acc);
    mlp_k<<<mlB, 512, MLP_SMEM_BYTES>>>(acc, w1_2, b1_2, w2_2, b2_2, nullptr,
                                        wh, bh, out);
}

// round 5
// speedup vs baseline: 1.7848x; 1.3106x over previous
#include <cuda_runtime.h>
#include <cuda_bf16.h>
#include <mma.h>
#include <cstdint>
using namespace nvcuda;

#define NN 50000
#define DD 128
#define NE 800000
#define PAD 136   // smem row stride (elements) -> conflict-free ldmatrix

// ---------------- device scratch (no allocations allowed) -------------------
__device__ float g_acc[NN * DD];
__device__ float g_hA[NN * DD];
__device__ float g_hB[NN * DD];
__device__ int   g_cnt[NN + 1];
__device__ int   g_cur[NN];
__device__ int   g_csr[NE];
__device__ int   g_is64;
// 7 matrices, each 64KB: bf16 hi[128*128] || lo[128*128], row-major [k][n]
__device__ __align__(16) char g_wp[7 * 65536];

// ---------------- fp32 -> bf16 hi/lo helpers --------------------------------
__device__ __forceinline__ uint32_t pbf2(float a, float b) {
    unsigned short ua = __bfloat16_as_ushort(__float2bfloat16_rn(a));
    unsigned short ub = __bfloat16_as_ushort(__float2bfloat16_rn(b));
    return (uint32_t)ua | ((uint32_t)ub << 16);
}
__device__ __forceinline__ float bres(float a) {
    return a - __bfloat162float(__float2bfloat16_rn(a));
}

// ---------------- preprocessing kernels -------------------------------------
__global__ void det_k(const unsigned int* __restrict__ w) {
    int is64 = 1;
    for (int j = 1; j < 64; j += 2)
        if (w[j] != 0u) { is64 = 0; break; }
    g_is64 = is64;
}

__global__ void hist_k(const unsigned int* __restrict__ w, int* __restrict__ cnt) {
    int e = blockIdx.x * blockDim.x + threadIdx.x;
    if (e >= NE) return;
    int d = g_is64 ? (int)w[2 * (NE + e)] : (int)w[NE + e];
    atomicAdd(&cnt[d + 1], 1);
}

__global__ void scan_k(int* __restrict__ cnt, int* __restrict__ cur) {
    __shared__ int part[1024];
    const int TOT = NN + 1;
    const int CH = (TOT + 1023) / 1024;
    int t = threadIdx.x;
    int beg = t * CH;
    int end = beg + CH; if (end > TOT) end = TOT;
    int sum = 0;
    for (int i = beg; i < end; i++) sum += cnt[i];
    part[t] = sum;
    __syncthreads();
    for (int off = 1; off < 1024; off <<= 1) {
        int add = (t >= off) ? part[t - off] : 0;
        __syncthreads();
        part[t] += add;
        __syncthreads();
    }
    int run = (t == 0) ? 0 : part[t - 1];
    for (int i = beg; i < end; i++) {
        run += cnt[i];
        cnt[i] = run;
        if (i < NN) cur[i] = run;
    }
}

__global__ void fill_k(const unsigned int* __restrict__ w,
                       int* __restrict__ cur, int* __restrict__ csr) {
    int e = blockIdx.x * blockDim.x + threadIdx.x;
    if (e >= NE) return;
    int s, d;
    if (g_is64) { s = (int)w[2 * e]; d = (int)w[2 * (NE + e)]; }
    else        { s = (int)w[e];     d = (int)w[NE + e]; }
    int p = atomicAdd(&cur[d], 1);
    csr[p] = s;
}

// Weight prep: fp32 W[k][n] -> bf16 hi/lo row-major [k][n]
__global__ void prep_w_k(const float* w0, const float* w1, const float* w2,
                         const float* w3, const float* w4, const float* w5,
                         const float* w6, char* __restrict__ wp) {
    const float* ws[7] = {w0, w1, w2, w3, w4, w5, w6};
    int m = blockIdx.y;
    const float* w = ws[m];
    __nv_bfloat16* dhi = (__nv_bfloat16*)(wp + (size_t)m * 65536);
    __nv_bfloat16* dlo = dhi + DD * DD;
    int idx = blockIdx.x * 256 + threadIdx.x;   // 0..4095
    int k = idx >> 5, n4 = idx & 31;
    float4 v = *(const float4*)(w + k * DD + n4 * 4);
    *(uint2*)(dhi + k * DD + n4 * 4) =
        make_uint2(pbf2(v.x, v.y), pbf2(v.z, v.w));
    *(uint2*)(dlo + k * DD + n4 * 4) =
        make_uint2(pbf2(bres(v.x), bres(v.y)), pbf2(bres(v.z), bres(v.w)));
}

// ---------------- aggregation (near L2 gather ceiling) -----------------------
__global__ __launch_bounds__(256) void agg_k(const float* __restrict__ h,
                                             const int* __restrict__ rs,
                                             const int* __restrict__ csr,
                                             float* __restrict__ acc) {
    int warp = threadIdx.x >> 5, lane = threadIdx.x & 31;
    int node = blockIdx.x * 8 + warp;
    if (node >= NN) return;
    float4 a = ((const float4*)(h + (size_t)node * DD))[lane];
    int beg = rs[node], end = rs[node + 1];
#pragma unroll 4
    for (int j = beg; j < end; j++) {
        int s = csr[j];
        float4 v = ((const float4*)(h + (size_t)s * DD))[lane];
        a.x += v.x; a.y += v.y; a.z += v.z; a.w += v.w;
    }
    ((float4*)(acc + (size_t)node * DD))[lane] = a;
}

// ---------------- WMMA bf16-split MLP (+ optional fused head) ----------------
// smem: Ahi | Alo | Whi | Wlo (bf16, 128 x PAD each) | F (fp32, 128 x PAD)
#define TILE_BF (128 * PAD)                       // elements
#define SM_TOTAL (4 * TILE_BF * 2 + TILE_BF * 4)  // 208896 bytes

__device__ __forceinline__ void split_store(__nv_bfloat16* Ahi, __nv_bfloat16* Alo,
                                            int row, int c, float4 v) {
    *(uint2*)(Ahi + row * PAD + c) =
        make_uint2(pbf2(v.x, v.y), pbf2(v.z, v.w));
    *(uint2*)(Alo + row * PAD + c) =
        make_uint2(pbf2(bres(v.x), bres(v.y)), pbf2(bres(v.z), bres(v.w)));
}

__device__ __forceinline__ void copy_w(const char* __restrict__ src,
                                       __nv_bfloat16* Whi, __nv_bfloat16* Wlo,
                                       int tid) {
    const uint4* s = (const uint4*)src;   // hi: 2048 uint4, lo: next 2048
#pragma unroll
    for (int i = tid; i < 2048; i += 512) {
        int row = i >> 4, seg = i & 15;
        *(uint4*)((char*)Whi + row * (PAD * 2) + seg * 16) = s[i];
        *(uint4*)((char*)Wlo + row * (PAD * 2) + seg * 16) = s[2048 + i];
    }
}

__device__ __forceinline__ void do_gemm(const __nv_bfloat16* Ahi,
                                        const __nv_bfloat16* Alo,
                                        const __nv_bfloat16* Whi,
                                        const __nv_bfloat16* Wlo,
                                        float* F, int wid) {
    int wm = (wid & 3) * 32, wn = (wid >> 2) * 32;
    wmma::fragment<wmma::accumulator, 16, 16, 16, float> acc[2][2];
#pragma unroll
    for (int mi = 0; mi < 2; mi++)
#pragma unroll
        for (int ni = 0; ni < 2; ni++) wmma::fill_fragment(acc[mi][ni], 0.0f);

#pragma unroll
    for (int k = 0; k < DD; k += 16) {
        wmma::fragment<wmma::matrix_a, 16, 16, 16, __nv_bfloat16, wmma::row_major> ah[2], al[2];
        wmma::fragment<wmma::matrix_b, 16, 16, 16, __nv_bfloat16, wmma::row_major> bh[2], bl[2];
#pragma unroll
        for (int mi = 0; mi < 2; mi++) {
            wmma::load_matrix_sync(ah[mi], Ahi + (wm + 16 * mi) * PAD + k, PAD);
            wmma::load_matrix_sync(al[mi], Alo + (wm + 16 * mi) * PAD + k, PAD);
        }
#pragma unroll
        for (int ni = 0; ni < 2; ni++) {
            wmma::load_matrix_sync(bh[ni], Whi + k * PAD + wn + 16 * ni, PAD);
            wmma::load_matrix_sync(bl[ni], Wlo + k * PAD + wn + 16 * ni, PAD);
        }
#pragma unroll
        for (int mi = 0; mi < 2; mi++)
#pragma unroll
            for (int ni = 0; ni < 2; ni++) {
                wmma::mma_sync(acc[mi][ni], ah[mi], bh[ni], acc[mi][ni]);
                wmma::mma_sync(acc[mi][ni], ah[mi], bl[ni], acc[mi][ni]);
                wmma::mma_sync(acc[mi][ni], al[mi], bh[ni], acc[mi][ni]);
            }
    }
#pragma unroll
    for (int mi = 0; mi < 2; mi++)
#pragma unroll
        for (int ni = 0; ni < 2; ni++)
            wmma::store_matrix_sync(F + (wm + 16 * mi) * PAD + wn + 16 * ni,
                                    acc[mi][ni], PAD, wmma::mem_row_major);
}

__global__ __launch_bounds__(512, 1) void mma_mlp_k(
    const float* __restrict__ X, const char* __restrict__ wp,
    int m1, int m2, int m3,
    const float* __restrict__ b1v, const float* __restrict__ b2v,
    const float* __restrict__ b3v,
    const float* __restrict__ RES, float* __restrict__ Y) {
    extern __shared__ char sm[];
    __nv_bfloat16* Ahi = (__nv_bfloat16*)sm;
    __nv_bfloat16* Alo = Ahi + TILE_BF;
    __nv_bfloat16* Whi = Alo + TILE_BF;
    __nv_bfloat16* Wlo = Whi + TILE_BF;
    float* F = (float*)(Wlo + TILE_BF);
    int tid = threadIdx.x, wid = tid >> 5;
    int r0 = blockIdx.x * 128;

    // stage A = X tile (hi/lo split)
#pragma unroll
    for (int i = tid; i < 4096; i += 512) {
        int row = i >> 5, c4 = i & 31;
        int grow = r0 + row;
        float4 v = make_float4(0.f, 0.f, 0.f, 0.f);
        if (grow < NN) v = *(const float4*)(X + (size_t)grow * DD + c4 * 4);
        split_store(Ahi, Alo, row, c4 * 4, v);
    }
    copy_w(wp + (size_t)m1 * 65536, Whi, Wlo, tid);
    __syncthreads();
    do_gemm(Ahi, Alo, Whi, Wlo, F, wid);
    __syncthreads();

    // t = relu(F + b1) -> A ; stage W2
#pragma unroll
    for (int i = tid; i < 4096; i += 512) {
        int row = i >> 5, c4 = i & 31;
        float4 v = *(float4*)(F + row * PAD + c4 * 4);
        float4 b = *(const float4*)(b1v + c4 * 4);
        v.x = fmaxf(v.x + b.x, 0.f);
        v.y = fmaxf(v.y + b.y, 0.f);
        v.z = fmaxf(v.z + b.z, 0.f);
        v.w = fmaxf(v.w + b.w, 0.f);
        split_store(Ahi, Alo, row, c4 * 4, v);
    }
    copy_w(wp + (size_t)m2 * 65536, Whi, Wlo, tid);
    __syncthreads();
    do_gemm(Ahi, Alo, Whi, Wlo, F, wid);
    __syncthreads();

    if (m3 < 0) {
        // epilogue: out = F + b2 (+ RES)
#pragma unroll
        for (int i = tid; i < 4096; i += 512) {
            int row = i >> 5, c4 = i & 31;
            int grow = r0 + row;
            if (grow >= NN) continue;
            float4 v = *(float4*)(F + row * PAD + c4 * 4);
            float4 b = *(const float4*)(b2v + c4 * 4);
            v.x += b.x; v.y += b.y; v.z += b.z; v.w += b.w;
            if (RES) {
                float4 rv = *(const float4*)(RES + (size_t)grow * DD + c4 * 4);
                v.x += rv.x; v.y += rv.y; v.z += rv.z; v.w += rv.w;
            }
            *(float4*)(Y + (size_t)grow * DD + c4 * 4) = v;
        }
    } else {
        // t2 = F + b2 -> A ; stage WH ; head GEMM ; out = F + b3
#pragma unroll
        for (int i = tid; i < 4096; i += 512) {
            int row = i >> 5, c4 = i & 31;
            float4 v = *(float4*)(F + row * PAD + c4 * 4);
            float4 b = *(const float4*)(b2v + c4 * 4);
            v.x += b.x; v.y += b.y; v.z += b.z; v.w += b.w;
            split_store(Ahi, Alo, row, c4 * 4, v);
        }
        copy_w(wp + (size_t)m3 * 65536, Whi, Wlo, tid);
        __syncthreads();
        do_gemm(Ahi, Alo, Whi, Wlo, F, wid);
        __syncthreads();
#pragma unroll
        for (int i = tid; i < 4096; i += 512) {
            int row = i >> 5, c4 = i & 31;
            int grow = r0 + row;
            if (grow >= NN) continue;
            float4 v = *(float4*)(F + row * PAD + c4 * 4);
            float4 b = *(const float4*)(b3v + c4 * 4);
            v.x += b.x; v.y += b.y; v.z += b.z; v.w += b.w;
            *(float4*)(Y + (size_t)grow * DD + c4 * 4) = v;
        }
    }
}

// ---------------- launch -----------------------------------------------------
extern "C" void kernel_launch(void* const* d_in, const int* in_sizes, int n_in,
                              void* d_out, int out_size) {
    const float* x         = (const float*)d_in[0];
    const unsigned int* ei = (const unsigned int*)d_in[1];
    const float* w1_0 = (const float*)d_in[2];
    const float* b1_0 = (const float*)d_in[3];
    const float* w2_0 = (const float*)d_in[4];
    const float* b2_0 = (const float*)d_in[5];
    const float* w1_1 = (const float*)d_in[6];
    const float* b1_1 = (const float*)d_in[7];
    const float* w2_1 = (const float*)d_in[8];
    const float* b2_1 = (const float*)d_in[9];
    const float* w1_2 = (const float*)d_in[10];
    const float* b1_2 = (const float*)d_in[11];
    const float* w2_2 = (const float*)d_in[12];
    const float* b2_2 = (const float*)d_in[13];
    const float* wh   = (const float*)d_in[14];
    const float* bh   = (const float*)d_in[15];
    float* out = (float*)d_out;

    float *acc, *hA, *hB;
    int *cnt, *cur, *csr;
    char* wp;
    cudaGetSymbolAddress((void**)&acc, g_acc);
    cudaGetSymbolAddress((void**)&hA, g_hA);
    cudaGetSymbolAddress((void**)&hB, g_hB);
    cudaGetSymbolAddress((void**)&cnt, g_cnt);
    cudaGetSymbolAddress((void**)&cur, g_cur);
    cudaGetSymbolAddress((void**)&csr, g_csr);
    cudaGetSymbolAddress((void**)&wp, g_wp);

    cudaFuncSetAttribute(mma_mlp_k, cudaFuncAttributeMaxDynamicSharedMemorySize,
                         SM_TOTAL);

    const int heB = (NE + 255) / 256;
    const int agB = (NN + 7) / 8;
    const int mlB = (NN + 127) / 128;   // 391

    // --- preprocessing ---
    det_k<<<1, 1>>>(ei);
    cudaMemsetAsync(cnt, 0, (NN + 1) * sizeof(int));
    hist_k<<<heB, 256>>>(ei, cnt);
    scan_k<<<1, 1024>>>(cnt, cur);
    fill_k<<<heB, 256>>>(ei, cur, csr);
    prep_w_k<<<dim3(16, 7), 256>>>(w1_0, w2_0, w1_1, w2_1, w1_2, w2_2, wh, wp);

    // --- layer 0 (residual = x) ---
    agg_k<<<agB, 256>>>(x, cnt, csr, acc);
    mma_mlp_k<<<mlB, 512, SM_TOTAL>>>(acc, wp, 0, 1, -1, b1_0, b2_0, nullptr, x, hA);
    // --- layer 1 (residual = hA) ---
    agg_k<<<agB, 256>>>(hA, cnt, csr, acc);
    mma_mlp_k<<<mlB, 512, SM_TOTAL>>>(acc, wp, 2, 3, -1, b1_1, b2_1, nullptr, hA, hB);
    // --- layer 2 (no residual) + fused head ---
    agg_k<<<agB, 256>>>(hB, cnt, csr, acc);
    mma_mlp_k<<<mlB, 512, SM_TOTAL>>>(acc, wp, 4, 5, 6, b1_2, b2_2, bh, nullptr, out);
}

// round 6
// speedup vs baseline: 1.9177x; 1.0745x over previous
#include <cuda_runtime.h>
#include <cuda_bf16.h>
#include <cstdint>

#define NN 50000
#define DD 128
#define NE 800000
#define WPAD 136                      // padded row length (bf16 elems)
#define WPM  (DD * WPAD * 2)          // bytes of one padded bf16 matrix = 34816

// ---------------- device scratch (no allocations allowed) -------------------
__device__ float g_acc[NN * DD];
__device__ float g_hA[NN * DD];
__device__ float g_hB[NN * DD];
__device__ int   g_cnt[NN + 1];
__device__ int   g_cur[NN];
__device__ int   g_csr[NE];
__device__ int   g_is64;
// 7 matrices: W^T padded bf16, hi (WPM bytes) || lo (WPM bytes) each
__device__ __align__(16) char g_wp[7 * 2 * WPM];

// ---------------- fp32 -> bf16 hi/lo helpers --------------------------------
__device__ __forceinline__ uint32_t pbf2(float a, float b) {
    unsigned short ua = __bfloat16_as_ushort(__float2bfloat16_rn(a));
    unsigned short ub = __bfloat16_as_ushort(__float2bfloat16_rn(b));
    return (uint32_t)ua | ((uint32_t)ub << 16);
}
__device__ __forceinline__ float bres(float a) {
    return a - __bfloat162float(__float2bfloat16_rn(a));
}

// ---------------- mma / ldmatrix primitives ---------------------------------
__device__ __forceinline__ void mma16816(float* c, uint32_t a0, uint32_t a1,
                                         uint32_t a2, uint32_t a3,
                                         uint32_t b0, uint32_t b1) {
    asm volatile(
        "mma.sync.aligned.m16n8k16.row.col.f32.bf16.bf16.f32 "
        "{%0,%1,%2,%3}, {%4,%5,%6,%7}, {%8,%9}, {%0,%1,%2,%3};"
        : "+f"(c[0]), "+f"(c[1]), "+f"(c[2]), "+f"(c[3])
        : "r"(a0), "r"(a1), "r"(a2), "r"(a3), "r"(b0), "r"(b1));
}

__device__ __forceinline__ void ldsm_x4(uint32_t& r0, uint32_t& r1,
                                        uint32_t& r2, uint32_t& r3,
                                        uint32_t addr) {
    asm volatile("ldmatrix.sync.aligned.m8n8.x4.shared.b16 {%0,%1,%2,%3}, [%4];"
                 : "=r"(r0), "=r"(r1), "=r"(r2), "=r"(r3) : "r"(addr));
}

__device__ __forceinline__ uint32_t smem_u32(const void* p) {
    uint32_t a;
    asm("{ .reg .u64 t; cvta.to.shared.u64 t, %1; cvt.u32.u64 %0, t; }"
        : "=r"(a) : "l"(p));
    return a;
}

// ---------------- preprocessing kernels -------------------------------------
__global__ void det_k(const unsigned int* __restrict__ w) {
    int is64 = 1;
    for (int j = 1; j < 64; j += 2)
        if (w[j] != 0u) { is64 = 0; break; }
    g_is64 = is64;
}

__global__ void hist_k(const unsigned int* __restrict__ w, int* __restrict__ cnt) {
    int e = blockIdx.x * blockDim.x + threadIdx.x;
    if (e >= NE) return;
    int d = g_is64 ? (int)w[2 * (NE + e)] : (int)w[NE + e];
    atomicAdd(&cnt[d + 1], 1);
}

__global__ void scan_k(int* __restrict__ cnt, int* __restrict__ cur) {
    __shared__ int part[1024];
    const int TOT = NN + 1;
    const int CH = (TOT + 1023) / 1024;
    int t = threadIdx.x;
    int beg = t * CH;
    int end = beg + CH; if (end > TOT) end = TOT;
    int sum = 0;
    for (int i = beg; i < end; i++) sum += cnt[i];
    part[t] = sum;
    __syncthreads();
    for (int off = 1; off < 1024; off <<= 1) {
        int add = (t >= off) ? part[t - off] : 0;
        __syncthreads();
        part[t] += add;
        __syncthreads();
    }
    int run = (t == 0) ? 0 : part[t - 1];
    for (int i = beg; i < end; i++) {
        run += cnt[i];
        cnt[i] = run;
        if (i < NN) cur[i] = run;
    }
}

__global__ void fill_k(const unsigned int* __restrict__ w,
                       int* __restrict__ cur, int* __restrict__ csr) {
    int e = blockIdx.x * blockDim.x + threadIdx.x;
    if (e >= NE) return;
    int s, d;
    if (g_is64) { s = (int)w[2 * e]; d = (int)w[2 * (NE + e)]; }
    else        { s = (int)w[e];     d = (int)w[NE + e]; }
    int p = atomicAdd(&cur[d], 1);
    csr[p] = s;
}

// Weight prep: fp32 W[k][n] -> W^T[n][k] bf16 hi/lo, rows padded to WPAD.
__global__ void prep_w_k(const float* w0, const float* w1, const float* w2,
                         const float* w3, const float* w4, const float* w5,
                         const float* w6, char* __restrict__ wp) {
    const float* ws[7] = {w0, w1, w2, w3, w4, w5, w6};
    int m = blockIdx.y;
    const float* w = ws[m];
    __nv_bfloat16* dhi = (__nv_bfloat16*)(wp + (size_t)m * 2 * WPM);
    __nv_bfloat16* dlo = (__nv_bfloat16*)((char*)dhi + WPM);
    int idx = blockIdx.x * 256 + threadIdx.x;   // 0..4095
    int n = idx >> 5, kq = idx & 31;
    int k = kq * 4;
    float v0 = w[(k + 0) * DD + n];
    float v1 = w[(k + 1) * DD + n];
    float v2 = w[(k + 2) * DD + n];
    float v3 = w[(k + 3) * DD + n];
    *(uint2*)(dhi + n * WPAD + k) =
        make_uint2(pbf2(v0, v1), pbf2(v2, v3));
    *(uint2*)(dlo + n * WPAD + k) =
        make_uint2(pbf2(bres(v0), bres(v1)), pbf2(bres(v2), bres(v3)));
}

// ---------------- aggregation (near L2 gather ceiling) -----------------------
__global__ __launch_bounds__(256) void agg_k(const float* __restrict__ h,
                                             const int* __restrict__ rs,
                                             const int* __restrict__ csr,
                                             float* __restrict__ acc) {
    int warp = threadIdx.x >> 5, lane = threadIdx.x & 31;
    int node = blockIdx.x * 8 + warp;
    if (node >= NN) return;
    float4 a = ((const float4*)(h + (size_t)node * DD))[lane];
    int beg = rs[node], end = rs[node + 1];
#pragma unroll 4
    for (int j = beg; j < end; j++) {
        int s = csr[j];
        float4 v = ((const float4*)(h + (size_t)s * DD))[lane];
        a.x += v.x; a.y += v.y; a.z += v.z; a.w += v.w;
    }
    ((float4*)(acc + (size_t)node * DD))[lane] = a;
}

// ---------------- register-pipelined bf16-split MLP --------------------------
__device__ __forceinline__ void copy_w(char* dst, const char* __restrict__ src,
                                       int tid) {
    const uint4* s = (const uint4*)src;
    uint4* d = (uint4*)dst;
#pragma unroll
    for (int i = tid; i < (2 * WPM) / 16; i += 128) d[i] = s[i];
}

// full 16x128 x 128 GEMM for one warp: C += (Ah+Al) @ (Wh+Wl), 3 products
__device__ __forceinline__ void gemm_reg(float c[16][4],
                                         const uint32_t Ah[8][4],
                                         const uint32_t Al[8][4],
                                         uint32_t wbase, int lane) {
    const int t = lane >> 3, r = lane & 7;
    const uint32_t rowoff = (uint32_t)(((t >> 1) * 8 + r) * WPAD + (t & 1) * 8) * 2;
#pragma unroll
    for (int kc = 0; kc < 8; kc++) {
#pragma unroll
        for (int np = 0; np < 8; np++) {
            uint32_t addr = wbase + rowoff +
                            (uint32_t)(np * 16 * WPAD + kc * 16) * 2;
            uint32_t h0, h1, h2, h3, l0, l1, l2, l3;
            ldsm_x4(h0, h1, h2, h3, addr);
            ldsm_x4(l0, l1, l2, l3, addr + WPM);
            mma16816(c[2 * np], Ah[kc][0], Ah[kc][1], Ah[kc][2], Ah[kc][3], h0, h1);
            mma16816(c[2 * np], Al[kc][0], Al[kc][1], Al[kc][2], Al[kc][3], h0, h1);
            mma16816(c[2 * np], Ah[kc][0], Ah[kc][1], Ah[kc][2], Ah[kc][3], l0, l1);
            mma16816(c[2 * np + 1], Ah[kc][0], Ah[kc][1], Ah[kc][2], Ah[kc][3], h2, h3);
            mma16816(c[2 * np + 1], Al[kc][0], Al[kc][1], Al[kc][2], Al[kc][3], h2, h3);
            mma16816(c[2 * np + 1], Ah[kc][0], Ah[kc][1], Ah[kc][2], Ah[kc][3], l2, l3);
        }
    }
}

__global__ __launch_bounds__(128, 3) void mma_mlp_k(
    const float* __restrict__ X, const char* __restrict__ wp,
    int m1, int m2, int m3,
    const float* __restrict__ b1v, const float* __restrict__ b2v,
    const float* __restrict__ b3v,
    const float* __restrict__ RES, float* __restrict__ Y) {
    extern __shared__ char sm[];
    const uint32_t smb = smem_u32(sm);
    const int tid = threadIdx.x;
    const int lane = tid & 31;
    const int gID = lane >> 2, tig = lane & 3;
    const int rbase = blockIdx.x * 64 + (tid >> 5) * 16;
    const int row0 = rbase + gID, row1 = row0 + 8;
    const bool v0 = row0 < NN, v1 = row1 < NN;

    // ---- load & split A (GEMM1 input) from gmem ----
    uint32_t Ah[8][4], Al[8][4];
#pragma unroll
    for (int kc = 0; kc < 8; kc++) {
        const float* x0 = X + (size_t)row0 * DD + kc * 16 + 2 * tig;
        const float* x1 = X + (size_t)row1 * DD + kc * 16 + 2 * tig;
        float2 p0 = v0 ? *(const float2*)x0 : make_float2(0.f, 0.f);
        float2 p1 = v1 ? *(const float2*)x1 : make_float2(0.f, 0.f);
        float2 p2 = v0 ? *(const float2*)(x0 + 8) : make_float2(0.f, 0.f);
        float2 p3 = v1 ? *(const float2*)(x1 + 8) : make_float2(0.f, 0.f);
        Ah[kc][0] = pbf2(p0.x, p0.y); Al[kc][0] = pbf2(bres(p0.x), bres(p0.y));
        Ah[kc][1] = pbf2(p1.x, p1.y); Al[kc][1] = pbf2(bres(p1.x), bres(p1.y));
        Ah[kc][2] = pbf2(p2.x, p2.y); Al[kc][2] = pbf2(bres(p2.x), bres(p2.y));
        Ah[kc][3] = pbf2(p3.x, p3.y); Al[kc][3] = pbf2(bres(p3.x), bres(p3.y));
    }

    float c[16][4];

    // ---- GEMM1 ----
    copy_w(sm, wp + (size_t)m1 * 2 * WPM, tid);
    __syncthreads();
#pragma unroll
    for (int i = 0; i < 16; i++)
#pragma unroll
        for (int j = 0; j < 4; j++) c[i][j] = 0.f;
    gemm_reg(c, Ah, Al, smb, lane);

    // epilogue1: relu(c + b1) -> A' (registers only)
#pragma unroll
    for (int nt = 0; nt < 16; nt++) {
        float2 b = *(const float2*)(b1v + nt * 8 + 2 * tig);
        float f0 = fmaxf(c[nt][0] + b.x, 0.f);
        float f1 = fmaxf(c[nt][1] + b.y, 0.f);
        float f2 = fmaxf(c[nt][2] + b.x, 0.f);
        float f3 = fmaxf(c[nt][3] + b.y, 0.f);
        int kc = nt >> 1, s = (nt & 1) * 2;
        Ah[kc][s]     = pbf2(f0, f1); Al[kc][s]     = pbf2(bres(f0), bres(f1));
        Ah[kc][s + 1] = pbf2(f2, f3); Al[kc][s + 1] = pbf2(bres(f2), bres(f3));
    }

    // ---- GEMM2 ----
    __syncthreads();
    copy_w(sm, wp + (size_t)m2 * 2 * WPM, tid);
    __syncthreads();
#pragma unroll
    for (int i = 0; i < 16; i++)
#pragma unroll
        for (int j = 0; j < 4; j++) c[i][j] = 0.f;
    gemm_reg(c, Ah, Al, smb, lane);

    if (m3 >= 0) {
        // epilogue2: A'' = c + b2 (no relu), then head GEMM
#pragma unroll
        for (int nt = 0; nt < 16; nt++) {
            float2 b = *(const float2*)(b2v + nt * 8 + 2 * tig);
            float f0 = c[nt][0] + b.x;
            float f1 = c[nt][1] + b.y;
            float f2 = c[nt][2] + b.x;
            float f3 = c[nt][3] + b.y;
            int kc = nt >> 1, s = (nt & 1) * 2;
            Ah[kc][s]     = pbf2(f0, f1); Al[kc][s]     = pbf2(bres(f0), bres(f1));
            Ah[kc][s + 1] = pbf2(f2, f3); Al[kc][s + 1] = pbf2(bres(f2), bres(f3));
        }
        __syncthreads();
        copy_w(sm, wp + (size_t)m3 * 2 * WPM, tid);
        __syncthreads();
#pragma unroll
        for (int i = 0; i < 16; i++)
#pragma unroll
            for (int j = 0; j < 4; j++) c[i][j] = 0.f;
        gemm_reg(c, Ah, Al, smb, lane);
        // final write: c + b3
#pragma unroll
        for (int nt = 0; nt < 16; nt++) {
            float2 b = *(const float2*)(b3v + nt * 8 + 2 * tig);
            int col = nt * 8 + 2 * tig;
            if (v0) *(float2*)(Y + (size_t)row0 * DD + col) =
                make_float2(c[nt][0] + b.x, c[nt][1] + b.y);
            if (v1) *(float2*)(Y + (size_t)row1 * DD + col) =
                make_float2(c[nt][2] + b.x, c[nt][3] + b.y);
        }
    } else {
        // write: c + b2 (+ RES)
#pragma unroll
        for (int nt = 0; nt < 16; nt++) {
            float2 b = *(const float2*)(b2v + nt * 8 + 2 * tig);
            int col = nt * 8 + 2 * tig;
            float o0 = c[nt][0] + b.x, o1 = c[nt][1] + b.y;
            float o2 = c[nt][2] + b.x, o3 = c[nt][3] + b.y;
            if (RES) {
                if (v0) {
                    float2 r = *(const float2*)(RES + (size_t)row0 * DD + col);
                    o0 += r.x; o1 += r.y;
                }
                if (v1) {
                    float2 r = *(const float2*)(RES + (size_t)row1 * DD + col);
                    o2 += r.x; o3 += r.y;
                }
            }
            if (v0) *(float2*)(Y + (size_t)row0 * DD + col) = make_float2(o0, o1);
            if (v1) *(float2*)(Y + (size_t)row1 * DD + col) = make_float2(o2, o3);
        }
    }
}

// ---------------- launch -----------------------------------------------------
extern "C" void kernel_launch(void* const* d_in, const int* in_sizes, int n_in,
                              void* d_out, int out_size) {
    const float* x         = (const float*)d_in[0];
    const unsigned int* ei = (const unsigned int*)d_in[1];
    const float* w1_0 = (const float*)d_in[2];
    const float* b1_0 = (const float*)d_in[3];
    const float* w2_0 = (const float*)d_in[4];
    const float* b2_0 = (const float*)d_in[5];
    const float* w1_1 = (const float*)d_in[6];
    const float* b1_1 = (const float*)d_in[7];
    const float* w2_1 = (const float*)d_in[8];
    const float* b2_1 = (const float*)d_in[9];
    const float* w1_2 = (const float*)d_in[10];
    const float* b1_2 = (const float*)d_in[11];
    const float* w2_2 = (const float*)d_in[12];
    const float* b2_2 = (const float*)d_in[13];
    const float* wh   = (const float*)d_in[14];
    const float* bh   = (const float*)d_in[15];
    float* out = (float*)d_out;

    float *acc, *hA, *hB;
    int *cnt, *cur, *csr;
    char* wp;
    cudaGetSymbolAddress((void**)&acc, g_acc);
    cudaGetSymbolAddress((void**)&hA, g_hA);
    cudaGetSymbolAddress((void**)&hB, g_hB);
    cudaGetSymbolAddress((void**)&cnt, g_cnt);
    cudaGetSymbolAddress((void**)&cur, g_cur);
    cudaGetSymbolAddress((void**)&csr, g_csr);
    cudaGetSymbolAddress((void**)&wp, g_wp);

    cudaFuncSetAttribute(mma_mlp_k, cudaFuncAttributeMaxDynamicSharedMemorySize,
                         2 * WPM);

    const int heB = (NE + 255) / 256;
    const int agB = (NN + 7) / 8;
    const int mlB = (NN + 63) / 64;   // 782

    // --- preprocessing ---
    det_k<<<1, 1>>>(ei);
    cudaMemsetAsync(cnt, 0, (NN + 1) * sizeof(int));
    hist_k<<<heB, 256>>>(ei, cnt);
    scan_k<<<1, 1024>>>(cnt, cur);
    fill_k<<<heB, 256>>>(ei, cur, csr);
    prep_w_k<<<dim3(16, 7), 256>>>(w1_0, w2_0, w1_1, w2_1, w1_2, w2_2, wh, wp);

    // --- layer 0 (residual = x) ---
    agg_k<<<agB, 256>>>(x, cnt, csr, acc);
    mma_mlp_k<<<mlB, 128, 2 * WPM>>>(acc, wp, 0, 1, -1, b1_0, b2_0, nullptr, x, hA);
    // --- layer 1 (residual = hA) ---
    agg_k<<<agB, 256>>>(hA, cnt, csr, acc);
    mma_mlp_k<<<mlB, 128, 2 * WPM>>>(acc, wp, 2, 3, -1, b1_1, b2_1, nullptr, hA, hB);
    // --- layer 2 (no residual) + fused head ---
    agg_k<<<agB, 256>>>(hB, cnt, csr, acc);
    mma_mlp_k<<<mlB, 128, 2 * WPM>>>(acc, wp, 4, 5, 6, b1_2, b2_2, bh, nullptr, out);
}